// round 17
// baseline (speedup 1.0000x reference)
#include <cuda_runtime.h>
#include <cuda_fp16.h>
#include <cstdint>

// SigCubicalEcc round 17: exact critical-cell decomposition.
// Every cell's filtration = value of its argmin pixel (min is exact), so
//   ECC_j = Sum_p c_p * sigma(lam*(t_j - x_p)),
// c_p = 1 - #edges-owned + #vertices-owned, a step-independent integer.
// Ownership = lexicographically-first argmin (strict < toward preceding
// neighbors, <= toward following) -- exact for ties. Boundary pads = +BIG.
// With h = tanh(100(t-x)) = 2*sigma-1 and Sum_p c_p = chi = 1:
//   ECC_j = 0.5 * Sum_p c_p h_p + 0.5.
// Prep kernel computes c_p (f16, 1.5MB scratch); main kernel is a pure
// weighted-tanh reduction: no min/max tree, no shfl, no halo.

#define HH 64
#define WW 64
#define NPIX (HH * WW)
#define STEPS 32
#define GROUPS 8
#define SPG 4                   // 4 steps = 2 half2 chains
#define THREADS 256
#define NWARP 8
#define ROWS_PER_WARP 8
#define NIMG 192
#define BIGF 1e30f

__device__ __half Cbuf[NIMG * NPIX];   // 1.5 MB scratch (L2-resident)

__device__ __forceinline__ uint32_t h2_as_u32(__half2 v) {
    return *reinterpret_cast<uint32_t*>(&v);
}
__device__ __forceinline__ __half2 u32_as_h2(uint32_t u) {
    return *reinterpret_cast<__half2*>(&u);
}
__device__ __forceinline__ __half2 tanh2_approx(__half2 v) {
    uint32_t r, u = h2_as_u32(v);
    asm("tanh.approx.f16x2 %0, %1;" : "=r"(r) : "r"(u));
    return u32_as_h2(r);
}

// ---- prep: c_p per pixel ----
__global__ __launch_bounds__(256)
void prep_kernel(const float* __restrict__ x) {
    int idx = blockIdx.x * 256 + threadIdx.x;
    if (idx >= NIMG * NPIX) return;
    int rem = idx & (NPIX - 1);
    int r = rem >> 6;
    int c = rem & 63;

    float v  = x[idx];
    float l  = (c > 0)              ? x[idx - 1]  : BIGF;
    float rt = (c < WW - 1)         ? x[idx + 1]  : BIGF;
    float u  = (r > 0)              ? x[idx - WW] : BIGF;
    float d  = (r < HH - 1)         ? x[idx + WW] : BIGF;
    float ul = (r > 0 && c > 0)     ? x[idx - WW - 1] : BIGF;
    float ur = (r > 0 && c < WW-1)  ? x[idx - WW + 1] : BIGF;
    float dl = (r < HH-1 && c > 0)  ? x[idx + WW - 1] : BIGF;
    float dr = (r < HH-1 && c < WW-1) ? x[idx + WW + 1] : BIGF;

    // edges: strict toward preceding (left, up), <= toward following
    bool eL = v <  l;
    bool eU = v <  u;
    bool eR = v <= rt;
    bool eD = v <= d;
    // vertices: first-among-tied in the 2x2 block
    bool tUL = eU && eL && (v <  ul);
    bool tUR = eU && eR && (v <  ur);
    bool tDL = eL && eD && (v <= dl);
    bool tDR = eR && eD && (v <= dr);

    int cp = 1 - ((int)eL + (int)eU + (int)eR + (int)eD)
               + ((int)tUL + (int)tUR + (int)tDL + (int)tDR);
    Cbuf[idx] = __float2half_rn((float)cp);
}

// ---- main: ECC_j = 0.5 * Sum c_p h + 0.5 ----
__global__ __launch_bounds__(THREADS, 8)
void sig_cubical_ecc_kernel(const float* __restrict__ x, float* __restrict__ out) {
    __shared__ float red[NWARP][SPG];

    const int img   = blockIdx.x >> 3;           // / GROUPS
    const int group = blockIdx.x & (GROUPS - 1);
    const int tid   = threadIdx.x;
    const int lane  = tid & 31;
    const int warp  = tid >> 5;

    const float HL = 100.0f;                     // LAM / 2

    const int j0 = group * SPG;
    const float A0 = HL * (0.02f + (float)(j0 + 0) * (0.26f / 31.0f));
    const float A1 = HL * (0.02f + (float)(j0 + 1) * (0.26f / 31.0f));
    const float A2 = HL * (0.02f + (float)(j0 + 2) * (0.26f / 31.0f));
    const float A3 = HL * (0.02f + (float)(j0 + 3) * (0.26f / 31.0f));

    const float*  xi = x    + (size_t)img * NPIX + 2 * lane;
    const __half* ci = Cbuf + (size_t)img * NPIX + 2 * lane;
    const int r0 = warp * ROWS_PER_WARP;

    __half2 accA = __floats2half2_rn(0.0f, 0.0f);
    __half2 accB = accA;

#pragma unroll
    for (int i = 0; i < ROWS_PER_WARP; i++) {
        float2 xv = *reinterpret_cast<const float2*>(xi + (r0 + i) * WW);
        __half2 cp2 = *reinterpret_cast<const __half2*>(ci + (r0 + i) * WW);

        __half2 ha0 = tanh2_approx(__floats2half2_rn(fmaf(xv.x, -HL, A0),
                                                     fmaf(xv.x, -HL, A1)));
        __half2 ha1 = tanh2_approx(__floats2half2_rn(fmaf(xv.y, -HL, A0),
                                                     fmaf(xv.y, -HL, A1)));
        __half2 hb0 = tanh2_approx(__floats2half2_rn(fmaf(xv.x, -HL, A2),
                                                     fmaf(xv.x, -HL, A3)));
        __half2 hb1 = tanh2_approx(__floats2half2_rn(fmaf(xv.y, -HL, A2),
                                                     fmaf(xv.y, -HL, A3)));

        __half2 c0 = __low2half2(cp2);    // (c_p0, c_p0)
        __half2 c1 = __high2half2(cp2);   // (c_p1, c_p1)

        accA = __hfma2(c0, ha0, accA);
        accA = __hfma2(c1, ha1, accA);
        accB = __hfma2(c0, hb0, accB);
        accB = __hfma2(c1, hb1, accB);
    }

    // ---- convert once, warp reduce in f32, block reduce, store ----
    float2 fa = __half22float2(accA);
    float2 fb = __half22float2(accB);
    float a0 = fa.x, a1 = fa.y, a2 = fb.x, a3 = fb.y;
#pragma unroll
    for (int o = 16; o > 0; o >>= 1) {
        a0 += __shfl_xor_sync(0xffffffffu, a0, o);
        a1 += __shfl_xor_sync(0xffffffffu, a1, o);
        a2 += __shfl_xor_sync(0xffffffffu, a2, o);
        a3 += __shfl_xor_sync(0xffffffffu, a3, o);
    }
    if (lane == 0) {
        red[warp][0] = a0; red[warp][1] = a1;
        red[warp][2] = a2; red[warp][3] = a3;
    }
    __syncthreads();

    if (tid < SPG) {
        float s = 0.0f;
#pragma unroll
        for (int w = 0; w < NWARP; w++) s += red[w][tid];
        // ECC = 0.5 * Sum c_p h + 0.5 * Sum c_p, and Sum c_p = chi = 1
        out[img * STEPS + group * SPG + tid] = 0.5f * s + 0.5f;
    }
}

extern "C" void kernel_launch(void* const* d_in, const int* in_sizes, int n_in,
                              void* d_out, int out_size) {
    const float* x = (const float*)d_in[0];
    float* out = (float*)d_out;

    prep_kernel<<<(NIMG * NPIX + 255) / 256, 256>>>(x);
    sig_cubical_ecc_kernel<<<NIMG * GROUPS, THREADS>>>(x, out);
}